// round 2
// baseline (speedup 1.0000x reference)
#include <cuda_runtime.h>
#include <cstdint>

// Shapes: B=128, LQ=32, LK=512, D_MODEL=HIDDEN=1024, H=16, HEAD=64
#define NEG_INF_F (-4294967295.0f)  // -2^32+1 (rounds to -2^32 in f32, same as ref)

// Scratch (static device globals: allocation-free)
__device__ float g_Q[4096 * 1024];   //  16 MB  (LN'd Q)
__device__ float g_K[67108864];      // 256 MB  (LN'd K)
__device__ float g_V[67108864];      // 256 MB  (V + bias)
__device__ int   g_seq_is64;

// ---------------------------------------------------------------------------
// seq_ids dtype detector: if the buffer is int64 (values 0..99), every odd
// int32 word is 0. For an int32 buffer, odd words are random 0..99 (99% != 0).
// ---------------------------------------------------------------------------
__global__ void detect_seq_kernel(const int* __restrict__ seq)
{
    if (threadIdx.x == 0 && blockIdx.x == 0) {
        int is64 = 1;
        for (int i = 0; i < 1024; i++) {
            if (seq[2 * i + 1] != 0) { is64 = 0; break; }
        }
        g_seq_is64 = is64;
    }
}

// ---------------------------------------------------------------------------
// FP32 SIMT GEMM: C[M,1024] = A[M,1024] @ W[1024,1024] + bias, optional
// per-64-col LayerNorm. Block tile 128x128, BK=16, 256 threads, 8x8/thread.
// ---------------------------------------------------------------------------
__global__ __launch_bounds__(256) void gemm_ln_simt(
    const float* __restrict__ A, const float* __restrict__ W,
    const float* __restrict__ bias, const float* __restrict__ lnw,
    const float* __restrict__ lnb, float* __restrict__ C, int doLN)
{
    __shared__ float As[16][132];   // [k][m]
    __shared__ float Ws[16][132];   // [k][n]
    __shared__ float bias_s[128];
    __shared__ float lnw_s[64], lnb_s[64];

    const int tid = threadIdx.x;
    const int tx = tid & 15, ty = tid >> 4;      // 16x16 thread grid
    const int m0 = blockIdx.y * 128, n0 = blockIdx.x * 128;

    if (tid < 128)      bias_s[tid]      = bias[n0 + tid];
    else if (tid < 192) lnw_s[tid - 128] = lnw[tid - 128];
    else                lnb_s[tid - 192] = lnb[tid - 192];

    float acc[8][8];
#pragma unroll
    for (int i = 0; i < 8; i++)
#pragma unroll
        for (int j = 0; j < 8; j++) acc[i][j] = 0.f;

    for (int kb = 0; kb < 1024; kb += 16) {
        __syncthreads();
        // A tile: 128 rows x 16 k, transposed into As[k][m]
#pragma unroll
        for (int i = 0; i < 2; i++) {
            int idx = tid + i * 256;          // 0..511
            int m = idx >> 2, kq = idx & 3;   // m 0..127, kq 0..3
            float4 v = *(const float4*)(A + (size_t)(m0 + m) * 1024 + kb + kq * 4);
            As[kq * 4 + 0][m] = v.x;
            As[kq * 4 + 1][m] = v.y;
            As[kq * 4 + 2][m] = v.z;
            As[kq * 4 + 3][m] = v.w;
        }
        // W tile: 16 k x 128 n, direct
#pragma unroll
        for (int i = 0; i < 2; i++) {
            int idx = tid + i * 256;
            int k = idx >> 5, n4 = idx & 31;
            float4 v = *(const float4*)(W + (size_t)(kb + k) * 1024 + n0 + n4 * 4);
            *(float4*)&Ws[k][n4 * 4] = v;
        }
        __syncthreads();
#pragma unroll
        for (int k = 0; k < 16; k++) {
            float a[8], b[8];
            *(float4*)&a[0] = *(const float4*)&As[k][ty * 8];
            *(float4*)&a[4] = *(const float4*)&As[k][ty * 8 + 4];
            *(float4*)&b[0] = *(const float4*)&Ws[k][tx * 8];
            *(float4*)&b[4] = *(const float4*)&Ws[k][tx * 8 + 4];
#pragma unroll
            for (int i = 0; i < 8; i++)
#pragma unroll
                for (int j = 0; j < 8; j++) acc[i][j] += a[i] * b[j];
        }
    }

    // Epilogue: bias (+ per-head-64 LN), store.
    // Thread covers rows m0+ty*8..+7, cols n0+tx*8..+7. A head = 64 cols =
    // 8 consecutive tx; lanes differing in bits 0..2 form that tx-group.
#pragma unroll
    for (int i = 0; i < 8; i++) {
        float v[8];
        float s1 = 0.f, s2 = 0.f;
#pragma unroll
        for (int j = 0; j < 8; j++) {
            float x = acc[i][j] + bias_s[tx * 8 + j];
            v[j] = x;
            s1 += x; s2 += x * x;
        }
        float* outr = C + (size_t)(m0 + ty * 8 + i) * 1024 + n0 + tx * 8;
        if (doLN) {
            s1 += __shfl_xor_sync(0xffffffffu, s1, 1);
            s1 += __shfl_xor_sync(0xffffffffu, s1, 2);
            s1 += __shfl_xor_sync(0xffffffffu, s1, 4);
            s2 += __shfl_xor_sync(0xffffffffu, s2, 1);
            s2 += __shfl_xor_sync(0xffffffffu, s2, 2);
            s2 += __shfl_xor_sync(0xffffffffu, s2, 4);
            float mean = s1 * (1.f / 64.f);
            float var  = s2 * (1.f / 64.f) - mean * mean;
            float rstd = rsqrtf(var + 1e-12f);
            float y[8];
#pragma unroll
            for (int j = 0; j < 8; j++) {
                int cin = (tx & 7) * 8 + j;   // col within head (0..63)
                y[j] = (v[j] - mean) * rstd * lnw_s[cin] + lnb_s[cin];
            }
            *(float4*)(outr)     = make_float4(y[0], y[1], y[2], y[3]);
            *(float4*)(outr + 4) = make_float4(y[4], y[5], y[6], y[7]);
        } else {
            *(float4*)(outr)     = make_float4(v[0], v[1], v[2], v[3]);
            *(float4*)(outr + 4) = make_float4(v[4], v[5], v[6], v[7]);
        }
    }
}

// ---------------------------------------------------------------------------
// Attention: one block per (head h, batch b). 256 threads.
// smem: Qs[32][65], S[32][520], KV[128][65], padf[512]  (~108 KB)
// ---------------------------------------------------------------------------
__global__ __launch_bounds__(256) void attn_kernel(
    const int* __restrict__ seq, float* __restrict__ outp,
    float* __restrict__ attp)
{
    const int h = blockIdx.x >> 7;     // att index = h*B + b = blockIdx.x
    const int b = blockIdx.x & 127;

    extern __shared__ float sm[];
    float* Qs   = sm;                   // 32*65  = 2080
    float* S    = sm + 2080;            // 32*520 = 16640
    float* KV   = sm + 2080 + 16640;    // 128*65 = 8320
    float* padf = KV + 8320;            // 512

    const int tid = threadIdx.x;
    const int lane = tid & 31, warp = tid >> 5;

    const float* Qg = g_Q + (size_t)b * 32  * 1024 + h * 64;
    const float* Kg = g_K + (size_t)b * 512 * 1024 + h * 64;
    const float* Vg = g_V + (size_t)b * 512 * 1024 + h * 64;

    // load Q tile (32x64) and pad flags (dtype-adaptive)
    for (int i = tid; i < 512; i += 256) {
        int q = i >> 4, d4 = i & 15;
        float4 t4 = *(const float4*)(Qg + (size_t)q * 1024 + d4 * 4);
        float* p = Qs + q * 65 + d4 * 4;
        p[0] = t4.x; p[1] = t4.y; p[2] = t4.z; p[3] = t4.w;
    }
    {
        const int is64 = g_seq_is64;
        for (int k = tid; k < 512; k += 256) {
            int p;
            if (is64) {
                size_t e = 2 * ((size_t)b * 512 + k);
                p = (seq[e] == 0) && (seq[e + 1] == 0);
            } else {
                p = (seq[(size_t)b * 512 + k] == 0);
            }
            padf[k] = p ? 1.f : 0.f;
        }
    }

    // ---- scores: S[q][k] = mask ? NEG_INF : (Q.K)/8 ----
    const float scale = 0.125f;
    const int tq = warp * 4;
    for (int c = 0; c < 4; c++) {
        __syncthreads();
        for (int i = tid; i < 2048; i += 256) {
            int kk = i >> 4, d4 = i & 15;
            float4 t4 = *(const float4*)(Kg + (size_t)(c * 128 + kk) * 1024 + d4 * 4);
            float* p = KV + kk * 65 + d4 * 4;
            p[0] = t4.x; p[1] = t4.y; p[2] = t4.z; p[3] = t4.w;
        }
        __syncthreads();
        float a4[4][4];
#pragma unroll
        for (int i = 0; i < 4; i++)
#pragma unroll
            for (int j = 0; j < 4; j++) a4[i][j] = 0.f;
#pragma unroll
        for (int d = 0; d < 64; d++) {
            float qv[4], kv[4];
#pragma unroll
            for (int i = 0; i < 4; i++) qv[i] = Qs[(tq + i) * 65 + d];
#pragma unroll
            for (int j = 0; j < 4; j++) kv[j] = KV[(lane + 32 * j) * 65 + d];
#pragma unroll
            for (int i = 0; i < 4; i++)
#pragma unroll
                for (int j = 0; j < 4; j++) a4[i][j] += qv[i] * kv[j];
        }
#pragma unroll
        for (int i = 0; i < 4; i++)
#pragma unroll
            for (int j = 0; j < 4; j++) {
                int k = c * 128 + lane + 32 * j;
                float s = (padf[k] > 0.f) ? NEG_INF_F : a4[i][j] * scale;
                S[(tq + i) * 520 + k] = s;
            }
    }
    __syncthreads();

    // ---- softmax per row; write att to global + back to S ----
    for (int rr = 0; rr < 4; rr++) {
        int r = warp * 4 + rr;
        float vv[16];
        float m = -3.4e38f;
#pragma unroll
        for (int i = 0; i < 16; i++) {
            vv[i] = S[r * 520 + lane + 32 * i];
            m = fmaxf(m, vv[i]);
        }
#pragma unroll
        for (int off = 16; off > 0; off >>= 1)
            m = fmaxf(m, __shfl_xor_sync(0xffffffffu, m, off));
        float ssum = 0.f;
#pragma unroll
        for (int i = 0; i < 16; i++) {
            float e = expf(vv[i] - m);
            vv[i] = e;
            ssum += e;
        }
#pragma unroll
        for (int off = 16; off > 0; off >>= 1)
            ssum += __shfl_xor_sync(0xffffffffu, ssum, off);
        float inv = 1.f / ssum;
        float* arow = attp + (size_t)blockIdx.x * 16384 + (size_t)r * 512;
#pragma unroll
        for (int i = 0; i < 16; i++) {
            float a = vv[i] * inv;
            S[r * 520 + lane + 32 * i] = a;
            arow[lane + 32 * i] = a;
        }
    }

    // ---- out[q][d] = sum_k att[q][k] * V[k][d] ----
    const int q0 = warp * 4;
    const int d0 = lane * 2;
    float o[4][2];
#pragma unroll
    for (int i = 0; i < 4; i++) { o[i][0] = 0.f; o[i][1] = 0.f; }
    for (int c = 0; c < 4; c++) {
        __syncthreads();
        for (int i = tid; i < 2048; i += 256) {
            int kk = i >> 4, d4 = i & 15;
            float4 t4 = *(const float4*)(Vg + (size_t)(c * 128 + kk) * 1024 + d4 * 4);
            float* p = KV + kk * 65 + d4 * 4;
            p[0] = t4.x; p[1] = t4.y; p[2] = t4.z; p[3] = t4.w;
        }
        __syncthreads();
#pragma unroll 4
        for (int kk = 0; kk < 128; kk++) {
            float v0 = KV[kk * 65 + d0];
            float v1 = KV[kk * 65 + d0 + 1];
#pragma unroll
            for (int i = 0; i < 4; i++) {
                float av = S[(q0 + i) * 520 + c * 128 + kk];
                o[i][0] += av * v0;
                o[i][1] += av * v1;
            }
        }
    }
#pragma unroll
    for (int i = 0; i < 4; i++) {
        *(float2*)(outp + (size_t)(b * 32 + q0 + i) * 1024 + h * 64 + d0) =
            make_float2(o[i][0], o[i][1]);
    }
}

// ---------------------------------------------------------------------------
extern "C" void kernel_launch(void* const* d_in, const int* in_sizes, int n_in,
                              void* d_out, int out_size)
{
    const float* tq  = (const float*)d_in[0];
    const float* iv  = (const float*)d_in[1];
    const int*   seq = (const int*)d_in[2];
    const float* Wq  = (const float*)d_in[3];
    const float* bq  = (const float*)d_in[4];
    const float* Wk  = (const float*)d_in[5];
    const float* bk  = (const float*)d_in[6];
    const float* Wv  = (const float*)d_in[7];
    const float* bv  = (const float*)d_in[8];
    const float* lnw = (const float*)d_in[9];
    const float* lnb = (const float*)d_in[10];

    float* outp = (float*)d_out;
    float* attp = outp + (size_t)4096 * 1024;   // out first, then att_vec

    void *pQ, *pK, *pV;
    cudaGetSymbolAddress(&pQ, g_Q);
    cudaGetSymbolAddress(&pK, g_K);
    cudaGetSymbolAddress(&pV, g_V);

    const int attn_smem = (2080 + 16640 + 8320 + 512) * 4;  // 110208 B
    cudaFuncSetAttribute(attn_kernel,
                         cudaFuncAttributeMaxDynamicSharedMemorySize, attn_smem);

    detect_seq_kernel<<<1, 32>>>(seq);

    // Q projection + LN  (M = 4096)
    gemm_ln_simt<<<dim3(8, 32), 256>>>(tq, Wq, bq, lnw, lnb, (float*)pQ, 1);
    // K projection + LN  (M = 65536)
    gemm_ln_simt<<<dim3(8, 512), 256>>>(iv, Wk, bk, lnw, lnb, (float*)pK, 1);
    // V projection (bias only)
    gemm_ln_simt<<<dim3(8, 512), 256>>>(iv, Wv, bv, lnw, lnb, (float*)pV, 0);
    // attention: one block per (h, b)
    attn_kernel<<<2048, 256, attn_smem>>>(seq, outp, attp);
}

// round 3
// speedup vs baseline: 2.6666x; 2.6666x over previous
#include <cuda_runtime.h>
#include <cstdint>

// Shapes: B=128, LQ=32, LK=512, D_MODEL=HIDDEN=1024, H=16, HEAD=64
#define NEG_INF_F (-4294967295.0f)  // -2^32+1

// Scratch (static device globals: allocation-free)
__device__ float g_Q[4096 * 1024];   //  16 MB  (LN'd Q)
__device__ float g_K[67108864];      // 256 MB  (LN'd K)
__device__ float g_V[67108864];      // 256 MB  (V + bias)
__device__ int   g_seq_is64;

__device__ __forceinline__ float tf32r(float x) {
    uint32_t u;
    asm("cvt.rna.tf32.f32 %0, %1;" : "=r"(u) : "f"(x));
    return __uint_as_float(u);
}

// ---------------------------------------------------------------------------
// seq_ids dtype detector (proven in round 2)
// ---------------------------------------------------------------------------
__global__ void detect_seq_kernel(const int* __restrict__ seq)
{
    if (threadIdx.x == 0 && blockIdx.x == 0) {
        int is64 = 1;
        for (int i = 0; i < 1024; i++) {
            if (seq[2 * i + 1] != 0) { is64 = 0; break; }
        }
        g_seq_is64 = is64;
    }
}

// ---------------------------------------------------------------------------
// TF32 tensor-core GEMM: C[M,1024] = A[M,1024] @ W[1024,1024] + bias,
// optional per-64-col LayerNorm. Block tile 128x128, BK=32, 256 threads
// (8 warps as 4m x 2n, warp tile 32x64), mma.sync m16n8k8 tf32/f32.
// Double-buffered smem, register-staged global loads.
// ---------------------------------------------------------------------------
__global__ __launch_bounds__(256) void gemm_ln_mma(
    const float* __restrict__ A, const float* __restrict__ W,
    const float* __restrict__ bias, const float* __restrict__ lnw,
    const float* __restrict__ lnb, float* __restrict__ C, int doLN)
{
    extern __shared__ float sm[];
    float* As     = sm;                 // 2 * 128*36 = 9216 floats
    float* Bs     = sm + 9216;          // 2 * 32*136 = 8704 floats
    float* bias_s = sm + 9216 + 8704;   // 128
    float* lnw_s  = bias_s + 128;       // 64
    float* lnb_s  = lnw_s + 64;         // 64

    const int tid  = threadIdx.x;
    const int lane = tid & 31, warp = tid >> 5;
    const int wm = warp >> 1, wn = warp & 1;
    const int m0 = blockIdx.y * 128, n0 = blockIdx.x * 128;

    if (tid < 128)      bias_s[tid]       = bias[n0 + tid];
    else if (tid < 192) lnw_s[tid - 128]  = lnw[tid - 128];
    else                lnb_s[tid - 192]  = lnb[tid - 192];

    float acc[2][8][4];
#pragma unroll
    for (int mi = 0; mi < 2; mi++)
#pragma unroll
        for (int ni = 0; ni < 8; ni++)
#pragma unroll
            for (int j = 0; j < 4; j++) acc[mi][ni][j] = 0.f;

    float4 ra[4], rb[4];

    // prologue: k-tile 0
#pragma unroll
    for (int i = 0; i < 4; i++) {
        int s = tid + i * 256;
        ra[i] = *(const float4*)(A + (size_t)(m0 + (s >> 3)) * 1024 + (s & 7) * 4);
        rb[i] = *(const float4*)(W + (size_t)(s >> 5) * 1024 + n0 + (s & 31) * 4);
    }
    {
        float* Ab = As; float* Bb = Bs;
#pragma unroll
        for (int i = 0; i < 4; i++) {
            int s = tid + i * 256;
            float* p = Ab + (s >> 3) * 36 + (s & 7) * 4;
            p[0] = tf32r(ra[i].x); p[1] = tf32r(ra[i].y);
            p[2] = tf32r(ra[i].z); p[3] = tf32r(ra[i].w);
            float* q = Bb + (s >> 5) * 136 + (s & 31) * 4;
            q[0] = tf32r(rb[i].x); q[1] = tf32r(rb[i].y);
            q[2] = tf32r(rb[i].z); q[3] = tf32r(rb[i].w);
        }
    }
    __syncthreads();

    int cur = 0;
    for (int kt = 0; kt < 32; kt++) {
        if (kt < 31) {
            int kb = (kt + 1) * 32;
#pragma unroll
            for (int i = 0; i < 4; i++) {
                int s = tid + i * 256;
                ra[i] = *(const float4*)(A + (size_t)(m0 + (s >> 3)) * 1024 + kb + (s & 7) * 4);
                rb[i] = *(const float4*)(W + (size_t)(kb + (s >> 5)) * 1024 + n0 + (s & 31) * 4);
            }
        }
        const float* Ac = As + cur * 4608;
        const float* Bc = Bs + cur * 4352;
#pragma unroll
        for (int ks = 0; ks < 4; ks++) {
            const int k8 = ks * 8;
            uint32_t af[2][4];
#pragma unroll
            for (int mi = 0; mi < 2; mi++) {
                int r = wm * 32 + mi * 16 + (lane >> 2);
                af[mi][0] = __float_as_uint(Ac[r       * 36 + k8 +     (lane & 3)]);
                af[mi][1] = __float_as_uint(Ac[(r + 8) * 36 + k8 +     (lane & 3)]);
                af[mi][2] = __float_as_uint(Ac[r       * 36 + k8 + 4 + (lane & 3)]);
                af[mi][3] = __float_as_uint(Ac[(r + 8) * 36 + k8 + 4 + (lane & 3)]);
            }
#pragma unroll
            for (int ni = 0; ni < 8; ni++) {
                int col = wn * 64 + ni * 8 + (lane >> 2);
                uint32_t b0 = __float_as_uint(Bc[(k8 +     (lane & 3)) * 136 + col]);
                uint32_t b1 = __float_as_uint(Bc[(k8 + 4 + (lane & 3)) * 136 + col]);
#pragma unroll
                for (int mi = 0; mi < 2; mi++) {
                    asm volatile(
                        "mma.sync.aligned.m16n8k8.row.col.f32.tf32.tf32.f32 "
                        "{%0,%1,%2,%3},{%4,%5,%6,%7},{%8,%9},{%0,%1,%2,%3};"
                        : "+f"(acc[mi][ni][0]), "+f"(acc[mi][ni][1]),
                          "+f"(acc[mi][ni][2]), "+f"(acc[mi][ni][3])
                        : "r"(af[mi][0]), "r"(af[mi][1]), "r"(af[mi][2]), "r"(af[mi][3]),
                          "r"(b0), "r"(b1));
                }
            }
        }
        if (kt < 31) {
            float* Ab = As + (cur ^ 1) * 4608;
            float* Bb = Bs + (cur ^ 1) * 4352;
#pragma unroll
            for (int i = 0; i < 4; i++) {
                int s = tid + i * 256;
                float* p = Ab + (s >> 3) * 36 + (s & 7) * 4;
                p[0] = tf32r(ra[i].x); p[1] = tf32r(ra[i].y);
                p[2] = tf32r(ra[i].z); p[3] = tf32r(ra[i].w);
                float* q = Bb + (s >> 5) * 136 + (s & 31) * 4;
                q[0] = tf32r(rb[i].x); q[1] = tf32r(rb[i].y);
                q[2] = tf32r(rb[i].z); q[3] = tf32r(rb[i].w);
            }
            __syncthreads();
            cur ^= 1;
        }
    }

    // Epilogue: bias (+ per-head-64 LN), store.
    // Row r of the warp's n-tile (64 cols = one head) lives in the 4 lanes
    // with the same lane>>2; shuffle-xor over lane bits 0..1 reduces it.
#pragma unroll
    for (int mi = 0; mi < 2; mi++) {
#pragma unroll
        for (int hh = 0; hh < 2; hh++) {
            float v[16];
            float s1 = 0.f, s2 = 0.f;
#pragma unroll
            for (int ni = 0; ni < 8; ni++) {
#pragma unroll
                for (int j = 0; j < 2; j++) {
                    int col = wn * 64 + ni * 8 + 2 * (lane & 3) + j;
                    float x = acc[mi][ni][hh * 2 + j] + bias_s[col];
                    v[ni * 2 + j] = x;
                    s1 += x; s2 += x * x;
                }
            }
            int row = m0 + wm * 32 + mi * 16 + (lane >> 2) + hh * 8;
            float* outr = C + (size_t)row * 1024 + n0 + wn * 64;
            if (doLN) {
                s1 += __shfl_xor_sync(0xffffffffu, s1, 1);
                s1 += __shfl_xor_sync(0xffffffffu, s1, 2);
                s2 += __shfl_xor_sync(0xffffffffu, s2, 1);
                s2 += __shfl_xor_sync(0xffffffffu, s2, 2);
                float mean = s1 * (1.f / 64.f);
                float var  = s2 * (1.f / 64.f) - mean * mean;
                float rstd = rsqrtf(var + 1e-12f);
#pragma unroll
                for (int ni = 0; ni < 8; ni++) {
                    int cin = ni * 8 + 2 * (lane & 3);
                    float2 y;
                    y.x = (v[ni * 2]     - mean) * rstd * lnw_s[cin]     + lnb_s[cin];
                    y.y = (v[ni * 2 + 1] - mean) * rstd * lnw_s[cin + 1] + lnb_s[cin + 1];
                    *(float2*)(outr + ni * 8 + 2 * (lane & 3)) = y;
                }
            } else {
#pragma unroll
                for (int ni = 0; ni < 8; ni++) {
                    *(float2*)(outr + ni * 8 + 2 * (lane & 3)) =
                        make_float2(v[ni * 2], v[ni * 2 + 1]);
                }
            }
        }
    }
}

// ---------------------------------------------------------------------------
// Attention: one block per (head h, batch b). 256 threads.  (proven round 2)
// ---------------------------------------------------------------------------
__global__ __launch_bounds__(256) void attn_kernel(
    const int* __restrict__ seq, float* __restrict__ outp,
    float* __restrict__ attp)
{
    const int h = blockIdx.x >> 7;
    const int b = blockIdx.x & 127;

    extern __shared__ float sm[];
    float* Qs   = sm;                   // 32*65  = 2080
    float* S    = sm + 2080;            // 32*520 = 16640
    float* KV   = sm + 2080 + 16640;    // 128*65 = 8320
    float* padf = KV + 8320;            // 512

    const int tid = threadIdx.x;
    const int lane = tid & 31, warp = tid >> 5;

    const float* Qg = g_Q + (size_t)b * 32  * 1024 + h * 64;
    const float* Kg = g_K + (size_t)b * 512 * 1024 + h * 64;
    const float* Vg = g_V + (size_t)b * 512 * 1024 + h * 64;

    for (int i = tid; i < 512; i += 256) {
        int q = i >> 4, d4 = i & 15;
        float4 t4 = *(const float4*)(Qg + (size_t)q * 1024 + d4 * 4);
        float* p = Qs + q * 65 + d4 * 4;
        p[0] = t4.x; p[1] = t4.y; p[2] = t4.z; p[3] = t4.w;
    }
    {
        const int is64 = g_seq_is64;
        for (int k = tid; k < 512; k += 256) {
            int p;
            if (is64) {
                size_t e = 2 * ((size_t)b * 512 + k);
                p = (seq[e] == 0) && (seq[e + 1] == 0);
            } else {
                p = (seq[(size_t)b * 512 + k] == 0);
            }
            padf[k] = p ? 1.f : 0.f;
        }
    }

    const float scale = 0.125f;
    const int tq = warp * 4;
    for (int c = 0; c < 4; c++) {
        __syncthreads();
        for (int i = tid; i < 2048; i += 256) {
            int kk = i >> 4, d4 = i & 15;
            float4 t4 = *(const float4*)(Kg + (size_t)(c * 128 + kk) * 1024 + d4 * 4);
            float* p = KV + kk * 65 + d4 * 4;
            p[0] = t4.x; p[1] = t4.y; p[2] = t4.z; p[3] = t4.w;
        }
        __syncthreads();
        float a4[4][4];
#pragma unroll
        for (int i = 0; i < 4; i++)
#pragma unroll
            for (int j = 0; j < 4; j++) a4[i][j] = 0.f;
#pragma unroll
        for (int d = 0; d < 64; d++) {
            float qv[4], kv[4];
#pragma unroll
            for (int i = 0; i < 4; i++) qv[i] = Qs[(tq + i) * 65 + d];
#pragma unroll
            for (int j = 0; j < 4; j++) kv[j] = KV[(lane + 32 * j) * 65 + d];
#pragma unroll
            for (int i = 0; i < 4; i++)
#pragma unroll
                for (int j = 0; j < 4; j++) a4[i][j] += qv[i] * kv[j];
        }
#pragma unroll
        for (int i = 0; i < 4; i++)
#pragma unroll
            for (int j = 0; j < 4; j++) {
                int k = c * 128 + lane + 32 * j;
                float s = (padf[k] > 0.f) ? NEG_INF_F : a4[i][j] * scale;
                S[(tq + i) * 520 + k] = s;
            }
    }
    __syncthreads();

    for (int rr = 0; rr < 4; rr++) {
        int r = warp * 4 + rr;
        float vv[16];
        float m = -3.4e38f;
#pragma unroll
        for (int i = 0; i < 16; i++) {
            vv[i] = S[r * 520 + lane + 32 * i];
            m = fmaxf(m, vv[i]);
        }
#pragma unroll
        for (int off = 16; off > 0; off >>= 1)
            m = fmaxf(m, __shfl_xor_sync(0xffffffffu, m, off));
        float ssum = 0.f;
#pragma unroll
        for (int i = 0; i < 16; i++) {
            float e = expf(vv[i] - m);
            vv[i] = e;
            ssum += e;
        }
#pragma unroll
        for (int off = 16; off > 0; off >>= 1)
            ssum += __shfl_xor_sync(0xffffffffu, ssum, off);
        float inv = 1.f / ssum;
        float* arow = attp + (size_t)blockIdx.x * 16384 + (size_t)r * 512;
#pragma unroll
        for (int i = 0; i < 16; i++) {
            float a = vv[i] * inv;
            S[r * 520 + lane + 32 * i] = a;
            arow[lane + 32 * i] = a;
        }
    }

    const int q0 = warp * 4;
    const int d0 = lane * 2;
    float o[4][2];
#pragma unroll
    for (int i = 0; i < 4; i++) { o[i][0] = 0.f; o[i][1] = 0.f; }
    for (int c = 0; c < 4; c++) {
        __syncthreads();
        for (int i = tid; i < 2048; i += 256) {
            int kk = i >> 4, d4 = i & 15;
            float4 t4 = *(const float4*)(Vg + (size_t)(c * 128 + kk) * 1024 + d4 * 4);
            float* p = KV + kk * 65 + d4 * 4;
            p[0] = t4.x; p[1] = t4.y; p[2] = t4.z; p[3] = t4.w;
        }
        __syncthreads();
#pragma unroll 4
        for (int kk = 0; kk < 128; kk++) {
            float v0 = KV[kk * 65 + d0];
            float v1 = KV[kk * 65 + d0 + 1];
#pragma unroll
            for (int i = 0; i < 4; i++) {
                float av = S[(q0 + i) * 520 + c * 128 + kk];
                o[i][0] += av * v0;
                o[i][1] += av * v1;
            }
        }
    }
#pragma unroll
    for (int i = 0; i < 4; i++) {
        *(float2*)(outp + (size_t)(b * 32 + q0 + i) * 1024 + h * 64 + d0) =
            make_float2(o[i][0], o[i][1]);
    }
}

// ---------------------------------------------------------------------------
extern "C" void kernel_launch(void* const* d_in, const int* in_sizes, int n_in,
                              void* d_out, int out_size)
{
    const float* tq  = (const float*)d_in[0];
    const float* iv  = (const float*)d_in[1];
    const int*   seq = (const int*)d_in[2];
    const float* Wq  = (const float*)d_in[3];
    const float* bq  = (const float*)d_in[4];
    const float* Wk  = (const float*)d_in[5];
    const float* bk  = (const float*)d_in[6];
    const float* Wv  = (const float*)d_in[7];
    const float* bv  = (const float*)d_in[8];
    const float* lnw = (const float*)d_in[9];
    const float* lnb = (const float*)d_in[10];

    float* outp = (float*)d_out;
    float* attp = outp + (size_t)4096 * 1024;   // out first, then att_vec

    void *pQ, *pK, *pV;
    cudaGetSymbolAddress(&pQ, g_Q);
    cudaGetSymbolAddress(&pK, g_K);
    cudaGetSymbolAddress(&pV, g_V);

    const int gemm_smem = (9216 + 8704 + 128 + 64 + 64) * 4;   // 72704 B
    const int attn_smem = (2080 + 16640 + 8320 + 512) * 4;     // 110208 B
    cudaFuncSetAttribute(gemm_ln_mma,
                         cudaFuncAttributeMaxDynamicSharedMemorySize, gemm_smem);
    cudaFuncSetAttribute(attn_kernel,
                         cudaFuncAttributeMaxDynamicSharedMemorySize, attn_smem);

    detect_seq_kernel<<<1, 32>>>(seq);

    // Q projection + LN  (M = 4096)
    gemm_ln_mma<<<dim3(8, 32), 256, gemm_smem>>>(tq, Wq, bq, lnw, lnb,
                                                 (float*)pQ, 1);
    // K projection + LN  (M = 65536)
    gemm_ln_mma<<<dim3(8, 512), 256, gemm_smem>>>(iv, Wk, bk, lnw, lnb,
                                                  (float*)pK, 1);
    // V projection (bias only)
    gemm_ln_mma<<<dim3(8, 512), 256, gemm_smem>>>(iv, Wv, bv, lnw, lnb,
                                                  (float*)pV, 0);
    // attention: one block per (h, b)
    attn_kernel<<<2048, 256, attn_smem>>>(seq, outp, attp);
}